// round 4
// baseline (speedup 1.0000x reference)
#include <cuda_runtime.h>
#include <math.h>
#include <stdint.h>

#define C 8192
#define D 512
#define BM 128
#define BN 128
#define BK 16
#define NTILE (C / BN)   // 64 column tiles

// ---------------- scratch (__device__ globals; no allocations allowed) ------
__device__ float g_norm[C * D];          // normalized embeddings (16 MB)
__device__ float g_pm[NTILE * C];        // per (col-tile, row) partial max
__device__ float g_pz[NTILE * C];        // partial sum exp(s - local max)
__device__ float g_pmn[NTILE * C];       // partial min
__device__ int   g_pimax[NTILE * C];
__device__ int   g_pimin[NTILE * C];
__device__ float g_margin[C];
__device__ int   g_ms[C];
__device__ int   g_ls[C];
__device__ float g_terms[C];

// ---------------- 1. row L2-normalize --------------------------------------
__global__ void normalize_kernel(const float* __restrict__ g) {
    int r = blockIdx.x;
    int t = threadIdx.x;  // 128 threads, 4 floats each
    const float4* in = (const float4*)(g + (size_t)r * D);
    float4 v = in[t];
    float ss = v.x * v.x + v.y * v.y + v.z * v.z + v.w * v.w;
#pragma unroll
    for (int o = 16; o; o >>= 1) ss += __shfl_down_sync(0xffffffffu, ss, o);
    __shared__ float sh[4];
    if ((t & 31) == 0) sh[t >> 5] = ss;
    __syncthreads();
    float inv = 1.0f / sqrtf(sh[0] + sh[1] + sh[2] + sh[3]);
    v.x *= inv; v.y *= inv; v.z *= inv; v.w *= inv;
    ((float4*)(g_norm + (size_t)r * D))[t] = v;
}

// ---------------- 2. fused GEMM tile + online row stats --------------------
// Grid (NTILE, NTILE): block (bx,by) computes S tile rows[by*128) x cols[bx*128)
// in registers via packed fma.rn.f32x2 (2 fp32 FMAs per issue), then reduces
// per-row (max,argmax,min,argmin,Z) and writes one partial per (col-tile,row).
__global__ void __launch_bounds__(256) gemm_stats_kernel() {
    __shared__ float As[BK][BM];
    __shared__ float Bs[BK][BN];

    const int bx = blockIdx.x;         // column tile
    const int by = blockIdx.y;         // row tile
    const int tid = threadIdx.x;
    const int tx = tid & 15;           // 16 threads across columns
    const int ty = tid >> 4;           // 16 thread-groups across rows
    const int row0 = by * BM;
    const int col0 = bx * BN;

    // 8 rows x 4 column-pairs of packed f32x2 accumulators (= 8x8 fp32)
    unsigned long long acc2[8][4];
#pragma unroll
    for (int i = 0; i < 8; i++)
#pragma unroll
        for (int jj = 0; jj < 4; jj++) acc2[i][jj] = 0ull;  // {0.0f, 0.0f}

    const int lr = tid >> 2;           // 0..63
    const int lk = (tid & 3) * 4;      // 0,4,8,12

    for (int k0 = 0; k0 < D; k0 += BK) {
#pragma unroll
        for (int h = 0; h < 2; h++) {
            int rr = lr + h * 64;
            float4 a = *(const float4*)(g_norm + (size_t)(row0 + rr) * D + k0 + lk);
            As[lk + 0][rr] = a.x; As[lk + 1][rr] = a.y;
            As[lk + 2][rr] = a.z; As[lk + 3][rr] = a.w;
            float4 b = *(const float4*)(g_norm + (size_t)(col0 + rr) * D + k0 + lk);
            Bs[lk + 0][rr] = b.x; Bs[lk + 1][rr] = b.y;
            Bs[lk + 2][rr] = b.z; Bs[lk + 3][rr] = b.w;
        }
        __syncthreads();
#pragma unroll
        for (int kk = 0; kk < BK; kk++) {
            float a[8];
            *(float4*)(a)     = *(const float4*)&As[kk][ty * 8];
            *(float4*)(a + 4) = *(const float4*)&As[kk][ty * 8 + 4];
            // B column pairs: adjacent floats in shared -> one 8B load each
            unsigned long long b2[4];
#pragma unroll
            for (int jj = 0; jj < 4; jj++)
                b2[jj] = *(const unsigned long long*)&Bs[kk][tx * 8 + 2 * jj];
#pragma unroll
            for (int i = 0; i < 8; i++) {
                unsigned long long aa;
                asm("mov.b64 %0, {%1, %1};" : "=l"(aa) : "f"(a[i]));
#pragma unroll
                for (int jj = 0; jj < 4; jj++)
                    asm("fma.rn.f32x2 %0, %1, %2, %0;"
                        : "+l"(acc2[i][jj]) : "l"(aa), "l"(b2[jj]));
            }
        }
        __syncthreads();
    }

    // unpack packed accumulators -> acc[8][8] fp32 (lo half = even column)
    float acc[8][8];
#pragma unroll
    for (int i = 0; i < 8; i++)
#pragma unroll
        for (int jj = 0; jj < 4; jj++)
            asm("mov.b64 {%0, %1}, %2;"
                : "=f"(acc[i][2 * jj]), "=f"(acc[i][2 * jj + 1])
                : "l"(acc2[i][jj]));

    // --- per-row online stats over this tile --------------------------------
#pragma unroll
    for (int i = 0; i < 8; i++) {
        int grow = row0 + ty * 8 + i;
        float m = -1e30f, mn = 1e30f;
        int im = 0, imn = 0;
#pragma unroll
        for (int j = 0; j < 8; j++) {
            int gcol = col0 + tx * 8 + j;
            bool diag = (gcol == grow);
            float sv = acc[i][j];
            float smax_v = diag ? -1e30f : sv;   // excluded from max / Z
            float smin_v = diag ?  1e30f : sv;   // excluded from min
            if (smax_v > m)  { m = smax_v; im = gcol; }
            if (smin_v < mn) { mn = smin_v; imn = gcol; }
        }
        float z = 0.0f;
#pragma unroll
        for (int j = 0; j < 8; j++) {
            int gcol = col0 + tx * 8 + j;
            float sv = (gcol == grow) ? -1e30f : acc[i][j];
            z += __expf(sv - m);                 // diag term underflows to 0
        }
        // merge across the 16 lanes that share this row (shuffle width 16)
#pragma unroll
        for (int off = 8; off; off >>= 1) {
            float m2  = __shfl_down_sync(0xffffffffu, m,  off, 16);
            float z2  = __shfl_down_sync(0xffffffffu, z,  off, 16);
            int   im2 = __shfl_down_sync(0xffffffffu, im, off, 16);
            float mn2 = __shfl_down_sync(0xffffffffu, mn, off, 16);
            int  imn2 = __shfl_down_sync(0xffffffffu, imn, off, 16);
            float M = fmaxf(m, m2);
            z = z * __expf(m - M) + z2 * __expf(m2 - M);
            if (m2 > m)       im = im2;
            else if (m2 == m) im = min(im, im2);   // jnp.argmax: first index
            m = M;
            if (mn2 < mn)       { mn = mn2; imn = imn2; }
            else if (mn2 == mn) imn = min(imn, imn2);
        }
        if (tx == 0) {
            int idx = bx * C + grow;
            g_pm[idx] = m;  g_pz[idx] = z;  g_pmn[idx] = mn;
            g_pimax[idx] = im;  g_pimin[idx] = imn;
        }
    }
}

// ---------------- 3. deterministic per-row merge of NTILE partials ----------
__global__ void combine_kernel() {
    int r = blockIdx.x * blockDim.x + threadIdx.x;
    if (r >= C) return;
    float m = -1e30f, z = 0.0f, mn = 1e30f;
    int im = 0x7fffffff, imn = 0x7fffffff;
    for (int s = 0; s < NTILE; s++) {     // ascending col-tile => tie = min idx
        int idx = s * C + r;
        float m2 = g_pm[idx], z2 = g_pz[idx], mn2 = g_pmn[idx];
        int im2 = g_pimax[idx], imn2 = g_pimin[idx];
        float M = fmaxf(m, m2);
        z = z * __expf(m - M) + z2 * __expf(m2 - M);
        if (m2 > m)       im = im2;
        else if (m2 == m) im = min(im, im2);
        m = M;
        if (mn2 < mn)       { mn = mn2; imn = imn2; }
        else if (mn2 == mn) imn = min(imn, imn2);
    }
    // P[ms] = 1/Z ; P[ls] = exp(smin - M)/Z ; margin = (1 - exp(smin-M))/Z
    g_margin[r] = (1.0f - __expf(mn - m)) / z;
    g_ms[r] = im;
    g_ls[r] = imn;
}

// ---------------- 4. distances + relu term per row (warp per row) ----------
__global__ void dist_kernel(const float* __restrict__ w) {
    int warp = (blockIdx.x * blockDim.x + threadIdx.x) >> 5;
    int lane = threadIdx.x & 31;
    if (warp >= C) return;
    int r = warp;
    int ms = g_ms[r], ls = g_ls[r];
    const float4* wr = (const float4*)(w + (size_t)r  * D);
    const float4* wm = (const float4*)(w + (size_t)ms * D);
    const float4* wl = (const float4*)(w + (size_t)ls * D);
    float dms = 0.0f, dls = 0.0f;
#pragma unroll
    for (int i = lane; i < D / 4; i += 32) {
        float4 a = wr[i], b = wm[i], c = wl[i];
        float dx;
        dx = a.x - b.x; dms = fmaf(dx, dx, dms);
        dx = a.y - b.y; dms = fmaf(dx, dx, dms);
        dx = a.z - b.z; dms = fmaf(dx, dx, dms);
        dx = a.w - b.w; dms = fmaf(dx, dx, dms);
        dx = a.x - c.x; dls = fmaf(dx, dx, dls);
        dx = a.y - c.y; dls = fmaf(dx, dx, dls);
        dx = a.z - c.z; dls = fmaf(dx, dx, dls);
        dx = a.w - c.w; dls = fmaf(dx, dx, dls);
    }
#pragma unroll
    for (int o = 16; o; o >>= 1) {
        dms += __shfl_down_sync(0xffffffffu, dms, o);
        dls += __shfl_down_sync(0xffffffffu, dls, o);
    }
    if (lane == 0)
        g_terms[r] = fmaxf(0.0f, sqrtf(dms) - sqrtf(dls) + g_margin[r]);
}

// ---------------- 5. deterministic final mean ------------------------------
__global__ void reduce_kernel(float* __restrict__ out) {
    __shared__ float sh[1024];
    int t = threadIdx.x;
    float s = 0.0f;
    for (int i = t; i < C; i += 1024) s += g_terms[i];
    sh[t] = s;
    __syncthreads();
    for (int o = 512; o; o >>= 1) {
        if (t < o) sh[t] += sh[t + o];
        __syncthreads();
    }
    if (t == 0) out[0] = sh[0] / (float)C;
}

// ---------------- launch ----------------------------------------------------
extern "C" void kernel_launch(void* const* d_in, const int* in_sizes, int n_in,
                              void* d_out, int out_size) {
    const float* g = (const float*)d_in[0];  // gt_class_embeddings [8192,512]
    const float* w = (const float*)d_in[1];  // w                   [8192,512]
    float* out = (float*)d_out;

    normalize_kernel<<<C, 128>>>(g);
    dim3 grid(NTILE, NTILE);                 // 64 x 64 = 4096 blocks
    gemm_stats_kernel<<<grid, 256>>>();
    combine_kernel<<<C / 256, 256>>>();
    dist_kernel<<<C / 8, 256>>>(w);          // 8 warps/block, warp per row
    reduce_kernel<<<1, 1024>>>(out);
}

// round 6
// speedup vs baseline: 1.7791x; 1.7791x over previous
#include <cuda_runtime.h>
#include <math.h>
#include <stdint.h>

#define C 8192
#define D 512
#define BM 128
#define BN 128
#define BK 16
#define NTILE (C / BN)   // 64 tiles per dimension

// ---------------- scratch (__device__ globals; no allocations allowed) ------
__device__ float g_norm[C * D];          // normalized embeddings (16 MB)
__device__ float g_pm[NTILE * C];        // per (col-tile, row) partial max
__device__ float g_pz[NTILE * C];        // partial sum exp(s - local max)
__device__ float g_pmn[NTILE * C];       // partial min
__device__ int   g_pimax[NTILE * C];
__device__ int   g_pimin[NTILE * C];
__device__ float g_margin[C];
__device__ int   g_ms[C];
__device__ int   g_ls[C];
__device__ float g_terms[C];

// ---------------- 1. row L2-normalize --------------------------------------
__global__ void normalize_kernel(const float* __restrict__ g) {
    int r = blockIdx.x;
    int t = threadIdx.x;  // 128 threads, 4 floats each
    const float4* in = (const float4*)(g + (size_t)r * D);
    float4 v = in[t];
    float ss = v.x * v.x + v.y * v.y + v.z * v.z + v.w * v.w;
#pragma unroll
    for (int o = 16; o; o >>= 1) ss += __shfl_down_sync(0xffffffffu, ss, o);
    __shared__ float sh[4];
    if ((t & 31) == 0) sh[t >> 5] = ss;
    __syncthreads();
    float inv = 1.0f / sqrtf(sh[0] + sh[1] + sh[2] + sh[3]);
    v.x *= inv; v.y *= inv; v.z *= inv; v.w *= inv;
    ((float4*)(g_norm + (size_t)r * D))[t] = v;
}

// ---------------- 2. fused GEMM tile + online row/col stats (symmetric) -----
// Only tiles with by <= bx are computed (S is symmetric). Off-diagonal tiles
// emit row-stats into slot bx AND column-stats (the transpose view) into slot
// by. Diagonal tiles emit row-stats with diag masking into slot bx.
__global__ void __launch_bounds__(256) gemm_stats_kernel() {
    const int bx = blockIdx.x;         // column tile
    const int by = blockIdx.y;         // row tile
    if (by > bx) return;               // lower triangle handled by symmetry

    // shared buffer: mainloop uses As/Bs (16 KB); off-diag epilogue reuses it
    // for the 16x128 per-ty column-stat partials (40 KB).
    __shared__ __align__(16) unsigned char sh_raw[16 * 128 * 4 * 5];
    float (*As)[BM] = reinterpret_cast<float(*)[BM]>(sh_raw);
    float (*Bs)[BN] = reinterpret_cast<float(*)[BN]>(sh_raw + BK * BM * 4);
    float (*cM)[128]  = reinterpret_cast<float(*)[128]>(sh_raw);
    float (*cZ)[128]  = reinterpret_cast<float(*)[128]>(sh_raw + 8192);
    float (*cMn)[128] = reinterpret_cast<float(*)[128]>(sh_raw + 16384);
    int   (*cIm)[128] = reinterpret_cast<int(*)[128]>(sh_raw + 24576);
    int   (*cImn)[128]= reinterpret_cast<int(*)[128]>(sh_raw + 32768);

    const int tid = threadIdx.x;
    const int tx = tid & 15;           // 16 threads across columns
    const int ty = tid >> 4;           // 16 thread-groups across rows
    const int row0 = by * BM;
    const int col0 = bx * BN;

    // 8 rows x 4 column-pairs of packed f32x2 accumulators (= 8x8 fp32)
    unsigned long long acc2[8][4];
#pragma unroll
    for (int i = 0; i < 8; i++)
#pragma unroll
        for (int jj = 0; jj < 4; jj++) acc2[i][jj] = 0ull;

    const int lr = tid >> 2;           // 0..63
    const int lk = (tid & 3) * 4;      // 0,4,8,12

    for (int k0 = 0; k0 < D; k0 += BK) {
#pragma unroll
        for (int h = 0; h < 2; h++) {
            int rr = lr + h * 64;
            float4 a = *(const float4*)(g_norm + (size_t)(row0 + rr) * D + k0 + lk);
            As[lk + 0][rr] = a.x; As[lk + 1][rr] = a.y;
            As[lk + 2][rr] = a.z; As[lk + 3][rr] = a.w;
            float4 b = *(const float4*)(g_norm + (size_t)(col0 + rr) * D + k0 + lk);
            Bs[lk + 0][rr] = b.x; Bs[lk + 1][rr] = b.y;
            Bs[lk + 2][rr] = b.z; Bs[lk + 3][rr] = b.w;
        }
        __syncthreads();
#pragma unroll
        for (int kk = 0; kk < BK; kk++) {
            float a[8];
            *(float4*)(a)     = *(const float4*)&As[kk][ty * 8];
            *(float4*)(a + 4) = *(const float4*)&As[kk][ty * 8 + 4];
            unsigned long long b2[4];
#pragma unroll
            for (int jj = 0; jj < 4; jj++)
                b2[jj] = *(const unsigned long long*)&Bs[kk][tx * 8 + 2 * jj];
#pragma unroll
            for (int i = 0; i < 8; i++) {
                unsigned long long aa;
                asm("mov.b64 %0, {%1, %1};" : "=l"(aa) : "f"(a[i]));
#pragma unroll
                for (int jj = 0; jj < 4; jj++)
                    asm("fma.rn.f32x2 %0, %1, %2, %0;"
                        : "+l"(acc2[i][jj]) : "l"(aa), "l"(b2[jj]));
            }
        }
        __syncthreads();
    }

    // unpack packed accumulators -> acc[8][8] fp32
    float acc[8][8];
#pragma unroll
    for (int i = 0; i < 8; i++)
#pragma unroll
        for (int jj = 0; jj < 4; jj++)
            asm("mov.b64 {%0, %1}, %2;"
                : "=f"(acc[i][2 * jj]), "=f"(acc[i][2 * jj + 1])
                : "l"(acc2[i][jj]));

    // --- row stats (reduce over columns) -> slot bx -------------------------
#pragma unroll
    for (int i = 0; i < 8; i++) {
        int grow = row0 + ty * 8 + i;
        float m = -1e30f, mn = 1e30f;
        int im = 0, imn = 0;
#pragma unroll
        for (int j = 0; j < 8; j++) {
            int gcol = col0 + tx * 8 + j;
            bool diag = (gcol == grow);           // only possible when bx==by
            float sv = acc[i][j];
            float smax_v = diag ? -1e30f : sv;
            float smin_v = diag ?  1e30f : sv;
            if (smax_v > m)  { m = smax_v; im = gcol; }
            if (smin_v < mn) { mn = smin_v; imn = gcol; }
        }
        float z = 0.0f;
#pragma unroll
        for (int j = 0; j < 8; j++) {
            int gcol = col0 + tx * 8 + j;
            float sv = (gcol == grow) ? -1e30f : acc[i][j];
            z += __expf(sv - m);
        }
#pragma unroll
        for (int off = 8; off; off >>= 1) {
            float m2  = __shfl_down_sync(0xffffffffu, m,  off, 16);
            float z2  = __shfl_down_sync(0xffffffffu, z,  off, 16);
            int   im2 = __shfl_down_sync(0xffffffffu, im, off, 16);
            float mn2 = __shfl_down_sync(0xffffffffu, mn, off, 16);
            int  imn2 = __shfl_down_sync(0xffffffffu, imn, off, 16);
            float M = fmaxf(m, m2);
            z = z * __expf(m - M) + z2 * __expf(m2 - M);
            if (m2 > m)       im = im2;
            else if (m2 == m) im = min(im, im2);   // first-index tie
            m = M;
            if (mn2 < mn)       { mn = mn2; imn = imn2; }
            else if (mn2 == mn) imn = min(imn, imn2);
        }
        if (tx == 0) {
            int idx = bx * C + grow;
            g_pm[idx] = m;  g_pz[idx] = z;  g_pmn[idx] = mn;
            g_pimax[idx] = im;  g_pimin[idx] = imn;
        }
    }

    // --- column stats (transpose view) -> slot by, off-diagonal tiles only --
    if (by == bx) return;
    __syncthreads();   // everyone done with As/Bs + row stats; reuse sh_raw
#pragma unroll
    for (int j = 0; j < 8; j++) {
        float m = -1e30f, mn = 1e30f;
        int im = 0, imn = 0;
#pragma unroll
        for (int i = 0; i < 8; i++) {            // ascending global row index
            int gidx = row0 + ty * 8 + i;
            float sv = acc[i][j];
            if (sv > m)  { m = sv; im = gidx; }
            if (sv < mn) { mn = sv; imn = gidx; }
        }
        float z = 0.0f;
#pragma unroll
        for (int i = 0; i < 8; i++) z += __expf(acc[i][j] - m);
        int cc = tx * 8 + j;
        cM[ty][cc] = m;  cZ[ty][cc] = z;  cMn[ty][cc] = mn;
        cIm[ty][cc] = im;  cImn[ty][cc] = imn;
    }
    __syncthreads();
    if (tid < 128) {                              // one thread per S-row (=col)
        int cc = tid;
        float m = -1e30f, z = 0.0f, mn = 1e30f;
        int im = 0x7fffffff, imn = 0x7fffffff;
        for (int t = 0; t < 16; t++) {            // ascending ty => first-index tie
            float m2 = cM[t][cc], z2 = cZ[t][cc], mn2 = cMn[t][cc];
            int im2 = cIm[t][cc], imn2 = cImn[t][cc];
            float M = fmaxf(m, m2);
            z = z * __expf(m - M) + z2 * __expf(m2 - M);
            if (m2 > m)       im = im2;
            else if (m2 == m) im = min(im, im2);
            m = M;
            if (mn2 < mn)       { mn = mn2; imn = imn2; }
            else if (mn2 == mn) imn = min(imn, imn2);
        }
        int idx = by * C + (col0 + cc);           // stats for S-row col0+cc, cols [row0,row0+128)
        g_pm[idx] = m;  g_pz[idx] = z;  g_pmn[idx] = mn;
        g_pimax[idx] = im;  g_pimin[idx] = imn;
    }
}

// ---------------- 3. deterministic per-row merge of NTILE partials ----------
__global__ void combine_kernel() {
    int r = blockIdx.x * blockDim.x + threadIdx.x;
    if (r >= C) return;
    float m = -1e30f, z = 0.0f, mn = 1e30f;
    int im = 0x7fffffff, imn = 0x7fffffff;
    for (int s = 0; s < NTILE; s++) {     // ascending col-tile => tie = min idx
        int idx = s * C + r;
        float m2 = g_pm[idx], z2 = g_pz[idx], mn2 = g_pmn[idx];
        int im2 = g_pimax[idx], imn2 = g_pimin[idx];
        float M = fmaxf(m, m2);
        z = z * __expf(m - M) + z2 * __expf(m2 - M);
        if (m2 > m)       im = im2;
        else if (m2 == m) im = min(im, im2);
        m = M;
        if (mn2 < mn)       { mn = mn2; imn = imn2; }
        else if (mn2 == mn) imn = min(imn, imn2);
    }
    // P[ms] = 1/Z ; P[ls] = exp(smin - M)/Z ; margin = (1 - exp(smin-M))/Z
    g_margin[r] = (1.0f - __expf(mn - m)) / z;
    g_ms[r] = im;
    g_ls[r] = imn;
}

// ---------------- 4. distances + relu term per row (warp per row) ----------
__global__ void dist_kernel(const float* __restrict__ w) {
    int warp = (blockIdx.x * blockDim.x + threadIdx.x) >> 5;
    int lane = threadIdx.x & 31;
    if (warp >= C) return;
    int r = warp;
    int ms = g_ms[r], ls = g_ls[r];
    const float4* wr = (const float4*)(w + (size_t)r  * D);
    const float4* wm = (const float4*)(w + (size_t)ms * D);
    const float4* wl = (const float4*)(w + (size_t)ls * D);
    float dms = 0.0f, dls = 0.0f;
#pragma unroll
    for (int i = lane; i < D / 4; i += 32) {
        float4 a = wr[i], b = wm[i], c = wl[i];
        float dx;
        dx = a.x - b.x; dms = fmaf(dx, dx, dms);
        dx = a.y - b.y; dms = fmaf(dx, dx, dms);
        dx = a.z - b.z; dms = fmaf(dx, dx, dms);
        dx = a.w - b.w; dms = fmaf(dx, dx, dms);
        dx = a.x - c.x; dls = fmaf(dx, dx, dls);
        dx = a.y - c.y; dls = fmaf(dx, dx, dls);
        dx = a.z - c.z; dls = fmaf(dx, dx, dls);
        dx = a.w - c.w; dls = fmaf(dx, dx, dls);
    }
#pragma unroll
    for (int o = 16; o; o >>= 1) {
        dms += __shfl_down_sync(0xffffffffu, dms, o);
        dls += __shfl_down_sync(0xffffffffu, dls, o);
    }
    if (lane == 0)
        g_terms[r] = fmaxf(0.0f, sqrtf(dms) - sqrtf(dls) + g_margin[r]);
}

// ---------------- 5. deterministic final mean ------------------------------
__global__ void reduce_kernel(float* __restrict__ out) {
    __shared__ float sh[1024];
    int t = threadIdx.x;
    float s = 0.0f;
    for (int i = t; i < C; i += 1024) s += g_terms[i];
    sh[t] = s;
    __syncthreads();
    for (int o = 512; o; o >>= 1) {
        if (t < o) sh[t] += sh[t + o];
        __syncthreads();
    }
    if (t == 0) out[0] = sh[0] / (float)C;
}

// ---------------- launch ----------------------------------------------------
extern "C" void kernel_launch(void* const* d_in, const int* in_sizes, int n_in,
                              void* d_out, int out_size) {
    const float* g = (const float*)d_in[0];  // gt_class_embeddings [8192,512]
    const float* w = (const float*)d_in[1];  // w                   [8192,512]
    float* out = (float*)d_out;

    normalize_kernel<<<C, 128>>>(g);
    dim3 grid(NTILE, NTILE);                 // upper triangle does the work
    gemm_stats_kernel<<<grid, 256>>>();
    combine_kernel<<<C / 256, 256>>>();
    dist_kernel<<<C / 8, 256>>>(w);          // 8 warps/block, warp per row
    reduce_kernel<<<1, 1024>>>(out);
}

// round 7
// speedup vs baseline: 1.8910x; 1.0629x over previous
#include <cuda_runtime.h>
#include <math.h>
#include <stdint.h>

#define C 8192
#define D 512
#define BM 128
#define BN 128
#define BK 16
#define NTILE (C / BN)   // 64 tiles per dimension
#define NIT (D / BK)     // 32 mainloop iterations

// ---------------- scratch (__device__ globals; no allocations allowed) ------
__device__ float g_norm[C * D];          // normalized embeddings (16 MB)
__device__ float g_pm[NTILE * C];        // per (col-tile, row) partial max
__device__ float g_pz[NTILE * C];        // partial sum exp(s - local max)
__device__ float g_pmn[NTILE * C];       // partial min
__device__ int   g_pimax[NTILE * C];
__device__ int   g_pimin[NTILE * C];
__device__ float g_margin[C];
__device__ int   g_ms[C];
__device__ int   g_ls[C];
__device__ float g_terms[C];

// ---------------- 1. row L2-normalize --------------------------------------
__global__ void normalize_kernel(const float* __restrict__ g) {
    int r = blockIdx.x;
    int t = threadIdx.x;  // 128 threads, 4 floats each
    const float4* in = (const float4*)(g + (size_t)r * D);
    float4 v = in[t];
    float ss = v.x * v.x + v.y * v.y + v.z * v.z + v.w * v.w;
#pragma unroll
    for (int o = 16; o; o >>= 1) ss += __shfl_down_sync(0xffffffffu, ss, o);
    __shared__ float sh[4];
    if ((t & 31) == 0) sh[t >> 5] = ss;
    __syncthreads();
    float inv = 1.0f / sqrtf(sh[0] + sh[1] + sh[2] + sh[3]);
    v.x *= inv; v.y *= inv; v.z *= inv; v.w *= inv;
    ((float4*)(g_norm + (size_t)r * D))[t] = v;
}

// ---------------- 2. fused GEMM tile + online row/col stats (symmetric) -----
// Only tiles with by <= bx are computed (S is symmetric). Double-buffered
// smem + register prefetch: LDGs for iteration it+1 issue before compute of
// it, stores land in the idle stage, one __syncthreads per iteration.
__global__ void __launch_bounds__(256, 2) gemm_stats_kernel() {
    const int bx = blockIdx.x;         // column tile
    const int by = blockIdx.y;         // row tile
    if (by > bx) return;               // lower triangle handled by symmetry

    // 40 KB shared: mainloop uses two 16 KB As/Bs stages; off-diag epilogue
    // reuses the whole buffer for 16x128 per-ty column-stat partials.
    __shared__ __align__(16) unsigned char sh_raw[40960];
    float (*cM)[128]  = reinterpret_cast<float(*)[128]>(sh_raw);
    float (*cZ)[128]  = reinterpret_cast<float(*)[128]>(sh_raw + 8192);
    float (*cMn)[128] = reinterpret_cast<float(*)[128]>(sh_raw + 16384);
    int   (*cIm)[128] = reinterpret_cast<int(*)[128]>(sh_raw + 24576);
    int   (*cImn)[128]= reinterpret_cast<int(*)[128]>(sh_raw + 32768);

    const int tid = threadIdx.x;
    const int tx = tid & 15;           // 16 threads across columns
    const int ty = tid >> 4;           // 16 thread-groups across rows
    const int row0 = by * BM;
    const int col0 = bx * BN;

    // 8 rows x 4 column-pairs of packed f32x2 accumulators (= 8x8 fp32)
    unsigned long long acc2[8][4];
#pragma unroll
    for (int i = 0; i < 8; i++)
#pragma unroll
        for (int jj = 0; jj < 4; jj++) acc2[i][jj] = 0ull;

    const int lr = tid >> 2;           // 0..63
    const int lk = (tid & 3) * 4;      // 0,4,8,12

    const float* pA0 = g_norm + (size_t)(row0 + lr) * D + lk;
    const float* pA1 = pA0 + (size_t)64 * D;
    const float* pB0 = g_norm + (size_t)(col0 + lr) * D + lk;
    const float* pB1 = pB0 + (size_t)64 * D;

    float4 pa0, pa1, pb0, pb1;
    // prologue: load iteration 0 and stage into buffer 0
    pa0 = *(const float4*)(pA0);  pa1 = *(const float4*)(pA1);
    pb0 = *(const float4*)(pB0);  pb1 = *(const float4*)(pB1);
    {
        float (*A)[BM] = reinterpret_cast<float(*)[BM]>(sh_raw);
        float (*B)[BN] = reinterpret_cast<float(*)[BN]>(sh_raw + 8192);
        A[lk + 0][lr] = pa0.x; A[lk + 1][lr] = pa0.y;
        A[lk + 2][lr] = pa0.z; A[lk + 3][lr] = pa0.w;
        A[lk + 0][lr + 64] = pa1.x; A[lk + 1][lr + 64] = pa1.y;
        A[lk + 2][lr + 64] = pa1.z; A[lk + 3][lr + 64] = pa1.w;
        B[lk + 0][lr] = pb0.x; B[lk + 1][lr] = pb0.y;
        B[lk + 2][lr] = pb0.z; B[lk + 3][lr] = pb0.w;
        B[lk + 0][lr + 64] = pb1.x; B[lk + 1][lr + 64] = pb1.y;
        B[lk + 2][lr + 64] = pb1.z; B[lk + 3][lr + 64] = pb1.w;
    }

#pragma unroll 1
    for (int it = 0; it < NIT; it++) {
        __syncthreads();               // stage (it&1) visible; prev compute done
        if (it + 1 < NIT) {            // prefetch next iteration (hidden by FMAs)
            int k0 = (it + 1) * BK;
            pa0 = *(const float4*)(pA0 + k0);  pa1 = *(const float4*)(pA1 + k0);
            pb0 = *(const float4*)(pB0 + k0);  pb1 = *(const float4*)(pB1 + k0);
        }
        float (*As)[BM] = reinterpret_cast<float(*)[BM]>(sh_raw + (it & 1) * 16384);
        float (*Bs)[BN] = reinterpret_cast<float(*)[BN]>(sh_raw + (it & 1) * 16384 + 8192);
#pragma unroll
        for (int kk = 0; kk < BK; kk++) {
            float a[8];
            *(float4*)(a)     = *(const float4*)&As[kk][ty * 8];
            *(float4*)(a + 4) = *(const float4*)&As[kk][ty * 8 + 4];
            unsigned long long b2[4];
#pragma unroll
            for (int jj = 0; jj < 4; jj++)
                b2[jj] = *(const unsigned long long*)&Bs[kk][tx * 8 + 2 * jj];
#pragma unroll
            for (int i = 0; i < 8; i++) {
                unsigned long long aa;
                asm("mov.b64 %0, {%1, %1};" : "=l"(aa) : "f"(a[i]));
#pragma unroll
                for (int jj = 0; jj < 4; jj++)
                    asm("fma.rn.f32x2 %0, %1, %2, %0;"
                        : "+l"(acc2[i][jj]) : "l"(aa), "l"(b2[jj]));
            }
        }
        if (it + 1 < NIT) {            // stage next iteration into idle buffer
            float (*A)[BM] = reinterpret_cast<float(*)[BM]>(sh_raw + ((it + 1) & 1) * 16384);
            float (*B)[BN] = reinterpret_cast<float(*)[BN]>(sh_raw + ((it + 1) & 1) * 16384 + 8192);
            A[lk + 0][lr] = pa0.x; A[lk + 1][lr] = pa0.y;
            A[lk + 2][lr] = pa0.z; A[lk + 3][lr] = pa0.w;
            A[lk + 0][lr + 64] = pa1.x; A[lk + 1][lr + 64] = pa1.y;
            A[lk + 2][lr + 64] = pa1.z; A[lk + 3][lr + 64] = pa1.w;
            B[lk + 0][lr] = pb0.x; B[lk + 1][lr] = pb0.y;
            B[lk + 2][lr] = pb0.z; B[lk + 3][lr] = pb0.w;
            B[lk + 0][lr + 64] = pb1.x; B[lk + 1][lr + 64] = pb1.y;
            B[lk + 2][lr + 64] = pb1.z; B[lk + 3][lr + 64] = pb1.w;
        }
    }

    // unpack packed accumulators -> acc[8][8] fp32
    float acc[8][8];
#pragma unroll
    for (int i = 0; i < 8; i++)
#pragma unroll
        for (int jj = 0; jj < 4; jj++)
            asm("mov.b64 {%0, %1}, %2;"
                : "=f"(acc[i][2 * jj]), "=f"(acc[i][2 * jj + 1])
                : "l"(acc2[i][jj]));

    // --- row stats (reduce over columns) -> slot bx -------------------------
#pragma unroll
    for (int i = 0; i < 8; i++) {
        int grow = row0 + ty * 8 + i;
        float m = -1e30f, mn = 1e30f;
        int im = 0, imn = 0;
#pragma unroll
        for (int j = 0; j < 8; j++) {
            int gcol = col0 + tx * 8 + j;
            bool diag = (gcol == grow);           // only possible when bx==by
            float sv = acc[i][j];
            float smax_v = diag ? -1e30f : sv;
            float smin_v = diag ?  1e30f : sv;
            if (smax_v > m)  { m = smax_v; im = gcol; }
            if (smin_v < mn) { mn = smin_v; imn = gcol; }
        }
        float z = 0.0f;
#pragma unroll
        for (int j = 0; j < 8; j++) {
            int gcol = col0 + tx * 8 + j;
            float sv = (gcol == grow) ? -1e30f : acc[i][j];
            z += __expf(sv - m);
        }
#pragma unroll
        for (int off = 8; off; off >>= 1) {
            float m2  = __shfl_down_sync(0xffffffffu, m,  off, 16);
            float z2  = __shfl_down_sync(0xffffffffu, z,  off, 16);
            int   im2 = __shfl_down_sync(0xffffffffu, im, off, 16);
            float mn2 = __shfl_down_sync(0xffffffffu, mn, off, 16);
            int  imn2 = __shfl_down_sync(0xffffffffu, imn, off, 16);
            float M = fmaxf(m, m2);
            z = z * __expf(m - M) + z2 * __expf(m2 - M);
            if (m2 > m)       im = im2;
            else if (m2 == m) im = min(im, im2);   // first-index tie
            m = M;
            if (mn2 < mn)       { mn = mn2; imn = imn2; }
            else if (mn2 == mn) imn = min(imn, imn2);
        }
        if (tx == 0) {
            int idx = bx * C + grow;
            g_pm[idx] = m;  g_pz[idx] = z;  g_pmn[idx] = mn;
            g_pimax[idx] = im;  g_pimin[idx] = imn;
        }
    }

    // --- column stats (transpose view) -> slot by, off-diagonal tiles only --
    if (by == bx) return;
    __syncthreads();   // everyone done with As/Bs + row stats; reuse sh_raw
#pragma unroll
    for (int j = 0; j < 8; j++) {
        float m = -1e30f, mn = 1e30f;
        int im = 0, imn = 0;
#pragma unroll
        for (int i = 0; i < 8; i++) {            // ascending global row index
            int gidx = row0 + ty * 8 + i;
            float sv = acc[i][j];
            if (sv > m)  { m = sv; im = gidx; }
            if (sv < mn) { mn = sv; imn = gidx; }
        }
        float z = 0.0f;
#pragma unroll
        for (int i = 0; i < 8; i++) z += __expf(acc[i][j] - m);
        int cc = tx * 8 + j;
        cM[ty][cc] = m;  cZ[ty][cc] = z;  cMn[ty][cc] = mn;
        cIm[ty][cc] = im;  cImn[ty][cc] = imn;
    }
    __syncthreads();
    if (tid < 128) {                              // one thread per S-row (=col)
        int cc = tid;
        float m = -1e30f, z = 0.0f, mn = 1e30f;
        int im = 0x7fffffff, imn = 0x7fffffff;
        for (int t = 0; t < 16; t++) {            // ascending ty => first-index tie
            float m2 = cM[t][cc], z2 = cZ[t][cc], mn2 = cMn[t][cc];
            int im2 = cIm[t][cc], imn2 = cImn[t][cc];
            float M = fmaxf(m, m2);
            z = z * __expf(m - M) + z2 * __expf(m2 - M);
            if (m2 > m)       im = im2;
            else if (m2 == m) im = min(im, im2);
            m = M;
            if (mn2 < mn)       { mn = mn2; imn = imn2; }
            else if (mn2 == mn) imn = min(imn, imn2);
        }
        int idx = by * C + (col0 + cc);           // stats for S-row col0+cc, cols [row0,row0+128)
        g_pm[idx] = m;  g_pz[idx] = z;  g_pmn[idx] = mn;
        g_pimax[idx] = im;  g_pimin[idx] = imn;
    }
}

// ---------------- 3. deterministic per-row merge of NTILE partials ----------
__global__ void combine_kernel() {
    int r = blockIdx.x * blockDim.x + threadIdx.x;
    if (r >= C) return;
    float m = -1e30f, z = 0.0f, mn = 1e30f;
    int im = 0x7fffffff, imn = 0x7fffffff;
    for (int s = 0; s < NTILE; s++) {     // ascending col-tile => tie = min idx
        int idx = s * C + r;
        float m2 = g_pm[idx], z2 = g_pz[idx], mn2 = g_pmn[idx];
        int im2 = g_pimax[idx], imn2 = g_pimin[idx];
        float M = fmaxf(m, m2);
        z = z * __expf(m - M) + z2 * __expf(m2 - M);
        if (m2 > m)       im = im2;
        else if (m2 == m) im = min(im, im2);
        m = M;
        if (mn2 < mn)       { mn = mn2; imn = imn2; }
        else if (mn2 == mn) imn = min(imn, imn2);
    }
    // P[ms] = 1/Z ; P[ls] = exp(smin - M)/Z ; margin = (1 - exp(smin-M))/Z
    g_margin[r] = (1.0f - __expf(mn - m)) / z;
    g_ms[r] = im;
    g_ls[r] = imn;
}

// ---------------- 4. distances + relu term per row (warp per row) ----------
__global__ void dist_kernel(const float* __restrict__ w) {
    int warp = (blockIdx.x * blockDim.x + threadIdx.x) >> 5;
    int lane = threadIdx.x & 31;
    if (warp >= C) return;
    int r = warp;
    int ms = g_ms[r], ls = g_ls[r];
    const float4* wr = (const float4*)(w + (size_t)r  * D);
    const float4* wm = (const float4*)(w + (size_t)ms * D);
    const float4* wl = (const float4*)(w + (size_t)ls * D);
    float dms = 0.0f, dls = 0.0f;
#pragma unroll
    for (int i = lane; i < D / 4; i += 32) {
        float4 a = wr[i], b = wm[i], c = wl[i];
        float dx;
        dx = a.x - b.x; dms = fmaf(dx, dx, dms);
        dx = a.y - b.y; dms = fmaf(dx, dx, dms);
        dx = a.z - b.z; dms = fmaf(dx, dx, dms);
        dx = a.w - b.w; dms = fmaf(dx, dx, dms);
        dx = a.x - c.x; dls = fmaf(dx, dx, dls);
        dx = a.y - c.y; dls = fmaf(dx, dx, dls);
        dx = a.z - c.z; dls = fmaf(dx, dx, dls);
        dx = a.w - c.w; dls = fmaf(dx, dx, dls);
    }
#pragma unroll
    for (int o = 16; o; o >>= 1) {
        dms += __shfl_down_sync(0xffffffffu, dms, o);
        dls += __shfl_down_sync(0xffffffffu, dls, o);
    }
    if (lane == 0)
        g_terms[r] = fmaxf(0.0f, sqrtf(dms) - sqrtf(dls) + g_margin[r]);
}

// ---------------- 5. deterministic final mean ------------------------------
__global__ void reduce_kernel(float* __restrict__ out) {
    __shared__ float sh[1024];
    int t = threadIdx.x;
    float s = 0.0f;
    for (int i = t; i < C; i += 1024) s += g_terms[i];
    sh[t] = s;
    __syncthreads();
    for (int o = 512; o; o >>= 1) {
        if (t < o) sh[t] += sh[t + o];
        __syncthreads();
    }
    if (t == 0) out[0] = sh[0] / (float)C;
}

// ---------------- launch ----------------------------------------------------
extern "C" void kernel_launch(void* const* d_in, const int* in_sizes, int n_in,
                              void* d_out, int out_size) {
    const float* g = (const float*)d_in[0];  // gt_class_embeddings [8192,512]
    const float* w = (const float*)d_in[1];  // w                   [8192,512]
    float* out = (float*)d_out;

    normalize_kernel<<<C, 128>>>(g);
    dim3 grid(NTILE, NTILE);                 // upper triangle does the work
    gemm_stats_kernel<<<grid, 256>>>();
    combine_kernel<<<C / 256, 256>>>();
    dist_kernel<<<C / 8, 256>>>(w);          // 8 warps/block, warp per row
    reduce_kernel<<<1, 1024>>>(out);
}